// round 10
// baseline (speedup 1.0000x reference)
#include <cuda_runtime.h>
#include <math.h>

#define EMAX 4096
#define NB2  256
#define W    8
#define CAPW (EMAX*EMAX)
#define CAPC 65536                    /* candidate cap per rank */
#define PI_F   3.14159274101257324f
#define THR_F  0.08726646259971647f
#define BSCALE 81.48733086305042f     /* 256/pi */
#define INF_BITS 0x7F800000u

// ---- device scratch (no allocations allowed) ----
__device__ float4   g_i4[EMAX];        // (ang, nx, ny, c) by original edge idx
__device__ float2   g_mid[EMAX];
__device__ int      g_bine[EMAX];
__device__ unsigned g_bcnt[NB2], g_bcur[NB2];
__device__ unsigned g_boff[NB2 + 1];
__device__ unsigned g_bwoff[NB2 + 1];
__device__ float4   g_q4[EMAX];        // bucket-order: (ang, mx, my, bitcast(orig idx))
__device__ float    g_bufw[CAPW];      // window slots: dist or +inf
__device__ unsigned g_hc[256];         // coarse: float bits >> 24
__device__ unsigned g_h16[65536];      // fine: float bits >> 16
__device__ float    g_cand[3*CAPC];    // candidates per rank
__device__ unsigned g_candn[3];
__device__ unsigned g_p16[3], g_r16[3];
__device__ unsigned g_n;
__device__ unsigned g_done;
__device__ double   g_sum;

// 256-entry inclusive scan using first 256 of 512 threads.
__device__ __forceinline__ unsigned scan256(unsigned* sh, unsigned h)
{
    int t = threadIdx.x;
    if (t < 256) sh[t] = h;
    __syncthreads();
    #pragma unroll
    for (int off = 1; off < 256; off <<= 1) {
        unsigned v = 0;
        if (t < 256) { v = sh[t]; if (t >= off) v += sh[t - off]; }
        __syncthreads();
        if (t < 256) sh[t] = v;
        __syncthreads();
    }
    return (t < 256) ? sh[t] : 0u;
}

// ---------------------------------------------------------------------------
// K1: zero scratch + per-edge geometry + bucket counts.  <<<64,256>>>
// ---------------------------------------------------------------------------
__global__ void k_setup(const float* __restrict__ pos, const int* __restrict__ eidx, int E)
{
    int gtid = blockIdx.x * blockDim.x + threadIdx.x;     // 16384 threads
    int nt   = gridDim.x * blockDim.x;
    for (int k = gtid; k < 65536; k += nt) g_h16[k] = 0u;
    if (gtid < 256) g_hc[gtid] = 0u;
    if (gtid < NB2) { g_bcnt[gtid] = 0u; g_bcur[gtid] = 0u; }
    if (gtid < 3)   g_candn[gtid] = 0u;
    if (gtid == 0)  { g_sum = 0.0; g_done = 0u; g_n = 0u; }

    if (gtid < E) {
        int e = gtid;
        int s = eidx[e];
        int d = eidx[E + e];
        float sx = pos[2*s], sy = pos[2*s+1];
        float dx = pos[2*d], dy = pos[2*d+1];
        float vx = dx - sx, vy = dy - sy;
        float len = fmaxf(sqrtf(vx*vx + vy*vy), 1e-8f);
        float ux = vx / len, uy = vy / len;
        float a = atan2f(uy, ux);
        a = fmodf(a, PI_F);
        if (a < 0.f) a += PI_F;
        float nx = -uy, ny = ux;
        g_i4[e]  = make_float4(a, nx, ny, sx*nx + sy*ny);
        g_mid[e] = make_float2((sx + dx) * 0.5f, (sy + dy) * 0.5f);
        int b = (int)(a * BSCALE);
        if (b >= NB2) b = NB2 - 1;
        if (b < 0)    b = 0;
        g_bine[e] = b;
        atomicAdd(&g_bcnt[b], 1u);
    }
}

// ---------------------------------------------------------------------------
// K2: redundant per-block scans (bucket offsets + window-slot bases) +
//     bucket scatter.  <<<16,256>>>
// ---------------------------------------------------------------------------
__global__ void k_fill(int E)
{
    __shared__ unsigned sc[NB2];
    __shared__ unsigned sbo[NB2];
    __shared__ unsigned ssc[NB2];
    int t = threadIdx.x;

    unsigned c = g_bcnt[t];
    sc[t] = c;
    ssc[t] = c;
    __syncthreads();
    #pragma unroll
    for (int off = 1; off < NB2; off <<= 1) {
        unsigned v = ssc[t];
        unsigned a = (t >= off) ? ssc[t - off] : 0u;
        __syncthreads();
        ssc[t] = v + a;
        __syncthreads();
    }
    unsigned exc = ssc[t] - c;
    sbo[t] = exc;
    g_boff[t] = exc;
    if (t == NB2 - 1) g_boff[NB2] = ssc[NB2 - 1];
    __syncthreads();

    unsigned Wt = 0;
    #pragma unroll
    for (int d = -W; d <= W; d++) Wt += sc[(t + d + NB2) & (NB2 - 1)];
    unsigned prod = c * Wt;
    ssc[t] = prod;
    __syncthreads();
    #pragma unroll
    for (int off = 1; off < NB2; off <<= 1) {
        unsigned v = ssc[t];
        unsigned a = (t >= off) ? ssc[t - off] : 0u;
        __syncthreads();
        ssc[t] = v + a;
        __syncthreads();
    }
    g_bwoff[t] = ssc[t] - prod;
    if (t == NB2 - 1) g_bwoff[NB2] = ssc[NB2 - 1];
    __syncthreads();

    int e = blockIdx.x * blockDim.x + t;
    if (e < E) {
        int b = g_bine[e];
        unsigned slot = sbo[b] + atomicAdd(&g_bcur[b], 1u);
        float4 f = g_i4[e];
        float2 m = g_mid[e];
        g_q4[slot] = make_float4(f.x, m.x, m.y, __int_as_float(e));
    }
}

// ---------------------------------------------------------------------------
// K3: single enumeration, deterministic slots; coarse hist in shared,
//     16-bit fine hist via spread global REDs.  <<<256,512>>>
// ---------------------------------------------------------------------------
__global__ void __launch_bounds__(512) k_enum(int E)
{
    __shared__ unsigned sb[NB2 + 1];
    __shared__ unsigned sbw[NB2];
    __shared__ unsigned shc[256];
    int t = threadIdx.x;
    for (int k = t; k <= NB2; k += 512) sb[k] = g_boff[k];
    for (int k = t; k < NB2;  k += 512) sbw[k] = g_bwoff[k];
    if (t < 256) shc[t] = 0u;
    __syncthreads();

    int gw   = (blockIdx.x * blockDim.x + t) >> 5;
    int lane = t & 31;
    int nw   = (gridDim.x * blockDim.x) >> 5;

    for (int s = gw; s < E; s += nw) {
        float4 qs = g_q4[s];
        int u = __float_as_int(qs.w);
        float4 f = g_i4[u];
        float au = f.x, nxu = f.y, nyu = f.z, cu = f.w;
        int b = g_bine[u];
        int lo = b - W, hi = b + W;
        unsigned r0s, r0e, r1s = 0u, r1e = 0u;
        if (lo < 0)         { r0s = sb[lo + NB2]; r0e = sb[NB2]; r1s = sb[0]; r1e = sb[hi + 1]; }
        else if (hi >= NB2) { r0s = sb[lo];       r0e = sb[NB2]; r1s = sb[0]; r1e = sb[hi - NB2 + 1]; }
        else                { r0s = sb[lo];       r0e = sb[hi + 1]; }

        unsigned Wb   = (r0e - r0s) + (r1e - r1s);
        unsigned rank = (unsigned)s - sb[b];
        unsigned base = sbw[b] + rank * Wb;

        unsigned off = 0;
        #pragma unroll
        for (int pass = 0; pass < 2; pass++) {
            unsigned ks = pass ? r1s : r0s;
            unsigned ke = pass ? r1e : r0e;
            for (unsigned k = ks + lane; k < ke; k += 32) {
                float4 q = g_q4[k];
                int v = __float_as_int(q.w);
                float da   = fabsf(au - q.x);
                float circ = fminf(da, PI_F - da);
                float val  = __uint_as_float(INF_BITS);
                if (v > u && circ <= THR_F) {        // exact reference mask
                    val = fabsf(fmaf(nxu, q.y, fmaf(nyu, q.z, -cu)));
                    unsigned bits = __float_as_uint(val);
                    atomicAdd(&shc[bits >> 24], 1u);
                    atomicAdd(&g_h16[bits >> 16], 1u);
                }
                g_bufw[base + off + (k - ks)] = val;
            }
            off += (r0e - r0s);
        }
    }
    __syncthreads();
    if (t < 256) {
        unsigned v = shc[t];
        if (v) atomicAdd(&g_hc[t], v);
    }
}

// ---------------------------------------------------------------------------
// K4: redundant coarse+fine pick (256+256 bins) -> 16-bit prefix per rank;
//     ONE stream over buffer extracting candidates.  <<<128,512>>>
// ---------------------------------------------------------------------------
__global__ void __launch_bounds__(512) k_pick_collect()
{
    __shared__ unsigned ssc[256];
    __shared__ unsigned s_cb[3], s_rA[3], s_p16[3];
    int t = threadIdx.x;
    if (t < 3) { s_cb[t] = 0xFFFFFFFFu; s_p16[t] = 0xFFFFFFFFu; }

    // coarse level
    unsigned h   = (t < 256) ? g_hc[t] : 0u;
    unsigned inc = scan256(ssc, h);
    unsigned exc = inc - h;
    __shared__ unsigned s_n;
    if (t == 255) s_n = inc;
    __syncthreads();
    unsigned n = s_n;
    if (t == 0) g_n = n;
    if (!n) return;

    unsigned r[3];
    r[0] = (n/4 > 0u) ? (n/4 - 1u) : 0u;
    r[1] = n/2;
    unsigned q3i = (unsigned)((3ull * n) / 4ull);
    if (q3i > n - 1u) q3i = n - 1u;
    r[2] = q3i;

    if (t < 256) {
        #pragma unroll
        for (int st = 0; st < 3; st++)
            if (h && exc <= r[st] && r[st] < inc) { s_cb[st] = (unsigned)t; s_rA[st] = r[st] - exc; }
    }
    __syncthreads();

    // fine level: 256 children of each rank's coarse bin
    for (int st = 0; st < 3; st++) {
        unsigned cb  = s_cb[st];
        unsigned h2  = (t < 256) ? g_h16[(cb << 8) + t] : 0u;
        unsigned in2 = scan256(ssc, h2);
        unsigned ex2 = in2 - h2;
        unsigned rA  = s_rA[st];
        if (t < 256 && h2 && ex2 <= rA && rA < in2) {
            s_p16[st] = (cb << 8) | (unsigned)t;
            g_p16[st] = s_p16[st];                   // identical across blocks
            g_r16[st] = rA - ex2;
        }
        __syncthreads();
    }

    // single stream: extract candidates for all 3 ranks
    unsigned p0 = s_p16[0], p1 = s_p16[1], p2 = s_p16[2];
    unsigned T = g_bwoff[NB2];
    int stride = gridDim.x * blockDim.x;
    for (unsigned idx = blockIdx.x * blockDim.x + t; idx < T; idx += stride) {
        float vfl = g_bufw[idx];
        unsigned pf = __float_as_uint(vfl) >> 16;    // inf prefix 0x7F80 never matches
        if (pf == p0) { unsigned p = atomicAdd(&g_candn[0], 1u); if (p < CAPC) g_cand[p]          = vfl; }
        if (pf == p1) { unsigned p = atomicAdd(&g_candn[1], 1u); if (p < CAPC) g_cand[CAPC   + p] = vfl; }
        if (pf == p2) { unsigned p = atomicAdd(&g_candn[2], 1u); if (p < CAPC) g_cand[2*CAPC + p] = vfl; }
    }
}

// ---------------------------------------------------------------------------
// K5: redundant exact pick inside candidates (two 256-bin rounds per rank)
//     + hinge-loss stream + fused finalize.  <<<128,512>>>
// ---------------------------------------------------------------------------
__global__ void __launch_bounds__(512) k_loss(float* __restrict__ out)
{
    __shared__ unsigned sbin[256];
    __shared__ unsigned ssc[256];
    __shared__ float    sq[3];
    __shared__ unsigned s_b1[3];
    int t = threadIdx.x;
    unsigned n = g_n;

    double acc = 0.0;
    if (n) {
        for (int st = 0; st < 3; st++) {
            unsigned c  = g_candn[st]; if (c > CAPC) c = CAPC;
            unsigned r16 = g_r16[st];
            unsigned p16 = g_p16[st];
            const float* cd = &g_cand[st * CAPC];

            // round 1: bits [8:16)
            if (t < 256) sbin[t] = 0u;
            __syncthreads();
            for (unsigned i = t; i < c; i += 512)
                atomicAdd(&sbin[(__float_as_uint(cd[i]) >> 8) & 255u], 1u);
            __syncthreads();
            unsigned h   = (t < 256) ? sbin[t] : 0u;
            unsigned inc = scan256(ssc, h);
            unsigned exc = inc - h;
            if (t < 256 && h && exc <= r16 && r16 < inc) {
                s_b1[st] = (unsigned)t;
                sq[st]   = __uint_as_float(r16 - exc);   // stash remaining rank
            }
            __syncthreads();
            unsigned b1 = s_b1[st];
            unsigned r8 = __float_as_uint(sq[st]);

            // round 2: bits [0:8) among candidates with matching bits[8:16)
            if (t < 256) sbin[t] = 0u;
            __syncthreads();
            for (unsigned i = t; i < c; i += 512) {
                unsigned bits = __float_as_uint(cd[i]);
                if (((bits >> 8) & 255u) == b1) atomicAdd(&sbin[bits & 255u], 1u);
            }
            __syncthreads();
            h   = (t < 256) ? sbin[t] : 0u;
            inc = scan256(ssc, h);
            exc = inc - h;
            if (t < 256 && h && exc <= r8 && r8 < inc)
                sq[st] = __uint_as_float((p16 << 16) | (b1 << 8) | (unsigned)t);
            __syncthreads();
        }

        float mu = sq[1];
        float margin = fmaxf(sq[2] - sq[0], 1e-6f) * 0.75f;   // iqr * 0.5 * 1.5

        unsigned T = g_bwoff[NB2];
        int stride = gridDim.x * blockDim.x;
        for (unsigned idx = blockIdx.x * blockDim.x + t; idx < T; idx += stride) {
            float d = g_bufw[idx];
            if (__float_as_uint(d) < INF_BITS) {
                float hh = fabsf(d - mu) - margin;
                if (hh > 0.f) acc += (double)hh;
            }
        }
    }

    for (int o = 16; o; o >>= 1) acc += __shfl_down_sync(0xFFFFFFFFu, acc, o);
    __shared__ double shs[16];
    if ((t & 31) == 0) shs[t >> 5] = acc;
    __syncthreads();
    if (t < 32) {
        double v = (t < 16) ? shs[t] : 0.0;
        for (int o = 8; o; o >>= 1) v += __shfl_down_sync(0xFFFFFFFFu, v, o);
        if (t == 0 && v != 0.0) atomicAdd(&g_sum, v);
    }
    __shared__ bool last;
    if (t == 0) {
        __threadfence();
        last = (atomicAdd(&g_done, 1u) == gridDim.x - 1);
    }
    __syncthreads();
    if (last && t == 0) {
        __threadfence();
        double denom = (double)(n > 0u ? n : 1u);
        out[0] = (float)(*(volatile double*)&g_sum / denom);
    }
}

// ---------------------------------------------------------------------------
extern "C" void kernel_launch(void* const* d_in, const int* in_sizes, int n_in,
                              void* d_out, int out_size)
{
    const float* pos  = (const float*)d_in[0];   // node_positions (B*N, 2)
    // d_in[1] = adjacency: unused
    const int*   eidx = (const int*)d_in[2];     // edge_index (2, E)
    float* out = (float*)d_out;

    int E = in_sizes[2] / 2;
    if (E > EMAX) E = EMAX;

    k_setup<<<64, 256>>>(pos, eidx, E);
    k_fill<<<16, 256>>>(E);
    k_enum<<<256, 512>>>(E);
    k_pick_collect<<<128, 512>>>();
    k_loss<<<128, 512>>>(out);
}

// round 11
// speedup vs baseline: 2.9237x; 2.9237x over previous
#include <cuda_runtime.h>
#include <math.h>

#define EMAX 4096
#define NB2  256
#define W    8
#define CAPW (EMAX*EMAX)              /* worst-case window-slot buffer */
#define PI_F   3.14159274101257324f
#define THR_F  0.08726646259971647f
#define BSCALE 81.48733086305042f     /* 256/pi */
#define INF_BITS 0x7F800000u

// ---- device scratch (no allocations allowed) ----
__device__ float4   g_i4[EMAX];        // (ang, nx, ny, c) by original edge idx
__device__ float2   g_mid[EMAX];
__device__ int      g_bine[EMAX];
__device__ unsigned g_bcnt[NB2], g_bcur[NB2];
__device__ unsigned g_boff[NB2 + 1];
__device__ unsigned g_bwoff[NB2 + 1]; // window-slot base per bucket
__device__ float4   g_q4[EMAX];        // bucket-order: (ang, mx, my, bitcast(orig idx))
__device__ float    g_bufw[CAPW];      // window slots: dist or +inf
__device__ unsigned g_hA[2048];        // float bits [21..31]
__device__ unsigned g_hB[3 * 2048];    // bits [10..20] per rank
__device__ unsigned g_hC[3 * 1024];    // bits [0..9]  per rank
__device__ unsigned g_n;
__device__ unsigned g_pA[3], g_rA[3];
__device__ unsigned g_pB[3], g_rB[3];
__device__ unsigned g_done;
__device__ double   g_sum;

// ---------------------------------------------------------------------------
// K1: zero scratch + per-edge geometry + bucket counts.  <<<32,256>>>
// ---------------------------------------------------------------------------
__global__ void k_setup(const float* __restrict__ pos, const int* __restrict__ eidx, int E)
{
    int gtid = blockIdx.x * blockDim.x + threadIdx.x;
    int nt   = gridDim.x * blockDim.x;
    for (int k = gtid; k < 2048;   k += nt) g_hA[k] = 0u;
    for (int k = gtid; k < 3*2048; k += nt) g_hB[k] = 0u;
    for (int k = gtid; k < 3*1024; k += nt) g_hC[k] = 0u;
    if (gtid < NB2) { g_bcnt[gtid] = 0u; g_bcur[gtid] = 0u; }
    if (gtid == 0)  { g_sum = 0.0; g_done = 0u; g_n = 0u; }

    if (gtid < E) {
        int e = gtid;
        int s = eidx[e];
        int d = eidx[E + e];
        float sx = pos[2*s], sy = pos[2*s+1];
        float dx = pos[2*d], dy = pos[2*d+1];
        float vx = dx - sx, vy = dy - sy;
        float len = fmaxf(sqrtf(vx*vx + vy*vy), 1e-8f);
        float ux = vx / len, uy = vy / len;
        float a = atan2f(uy, ux);
        a = fmodf(a, PI_F);
        if (a < 0.f) a += PI_F;
        float nx = -uy, ny = ux;
        g_i4[e]  = make_float4(a, nx, ny, sx*nx + sy*ny);
        g_mid[e] = make_float2((sx + dx) * 0.5f, (sy + dy) * 0.5f);
        int b = (int)(a * BSCALE);
        if (b >= NB2) b = NB2 - 1;
        if (b < 0)    b = 0;
        g_bine[e] = b;
        atomicAdd(&g_bcnt[b], 1u);
    }
}

// ---------------------------------------------------------------------------
// K2: redundant per-block scans (bucket offsets + window-slot bases) +
//     bucket scatter.  <<<16,256>>>
// ---------------------------------------------------------------------------
__global__ void k_fill(int E)
{
    __shared__ unsigned sc[NB2];
    __shared__ unsigned sbo[NB2];
    __shared__ unsigned ssc[NB2];
    int t = threadIdx.x;

    unsigned c = g_bcnt[t];
    sc[t] = c;
    ssc[t] = c;
    __syncthreads();
    #pragma unroll
    for (int off = 1; off < NB2; off <<= 1) {
        unsigned v = ssc[t];
        unsigned a = (t >= off) ? ssc[t - off] : 0u;
        __syncthreads();
        ssc[t] = v + a;
        __syncthreads();
    }
    unsigned exc = ssc[t] - c;
    sbo[t] = exc;
    g_boff[t] = exc;
    if (t == NB2 - 1) g_boff[NB2] = ssc[NB2 - 1];
    __syncthreads();

    unsigned Wt = 0;
    #pragma unroll
    for (int d = -W; d <= W; d++) Wt += sc[(t + d + NB2) & (NB2 - 1)];
    unsigned prod = c * Wt;
    ssc[t] = prod;
    __syncthreads();
    #pragma unroll
    for (int off = 1; off < NB2; off <<= 1) {
        unsigned v = ssc[t];
        unsigned a = (t >= off) ? ssc[t - off] : 0u;
        __syncthreads();
        ssc[t] = v + a;
        __syncthreads();
    }
    g_bwoff[t] = ssc[t] - prod;
    if (t == NB2 - 1) g_bwoff[NB2] = ssc[NB2 - 1];
    __syncthreads();

    int e = blockIdx.x * blockDim.x + t;
    if (e < E) {
        int b = g_bine[e];
        unsigned slot = sbo[b] + atomicAdd(&g_bcur[b], 1u);
        float4 f = g_i4[e];
        float2 m = g_mid[e];
        g_q4[slot] = make_float4(f.x, m.x, m.y, __int_as_float(e));
    }
}

// ---------------------------------------------------------------------------
// K3: SINGLE enumeration — deterministic slots; shared 2048-bin level-A
//     histogram.  <<<256,512>>>
// ---------------------------------------------------------------------------
__global__ void __launch_bounds__(512) k_enum(int E)
{
    __shared__ unsigned sb[NB2 + 1];
    __shared__ unsigned sbw[NB2];
    __shared__ unsigned sh[2048];
    int t = threadIdx.x;
    for (int k = t; k <= NB2; k += 512) sb[k] = g_boff[k];
    for (int k = t; k < NB2;  k += 512) sbw[k] = g_bwoff[k];
    for (int k = t; k < 2048; k += 512) sh[k] = 0u;
    __syncthreads();

    int gw   = (blockIdx.x * blockDim.x + t) >> 5;
    int lane = t & 31;
    int nw   = (gridDim.x * blockDim.x) >> 5;

    for (int s = gw; s < E; s += nw) {
        float4 qs = g_q4[s];
        int u = __float_as_int(qs.w);
        float4 f = g_i4[u];
        float au = f.x, nxu = f.y, nyu = f.z, cu = f.w;
        int b = g_bine[u];
        int lo = b - W, hi = b + W;
        unsigned r0s, r0e, r1s = 0u, r1e = 0u;
        if (lo < 0)         { r0s = sb[lo + NB2]; r0e = sb[NB2]; r1s = sb[0]; r1e = sb[hi + 1]; }
        else if (hi >= NB2) { r0s = sb[lo];       r0e = sb[NB2]; r1s = sb[0]; r1e = sb[hi - NB2 + 1]; }
        else                { r0s = sb[lo];       r0e = sb[hi + 1]; }

        unsigned Wb   = (r0e - r0s) + (r1e - r1s);
        unsigned rank = (unsigned)s - sb[b];
        unsigned base = sbw[b] + rank * Wb;

        unsigned off = 0;
        #pragma unroll
        for (int pass = 0; pass < 2; pass++) {
            unsigned ks = pass ? r1s : r0s;
            unsigned ke = pass ? r1e : r0e;
            for (unsigned k = ks + lane; k < ke; k += 32) {
                float4 q = g_q4[k];
                int v = __float_as_int(q.w);
                float da   = fabsf(au - q.x);
                float circ = fminf(da, PI_F - da);
                float val  = __uint_as_float(INF_BITS);
                if (v > u && circ <= THR_F) {        // exact reference mask
                    val = fabsf(fmaf(nxu, q.y, fmaf(nyu, q.z, -cu)));
                    atomicAdd(&sh[__float_as_uint(val) >> 21], 1u);
                }
                g_bufw[base + off + (k - ks)] = val;
            }
            off += (r0e - r0s);
        }
    }
    __syncthreads();
    for (int k = t; k < 2048; k += 512) {
        unsigned v = sh[k];
        if (v) atomicAdd(&g_hA[k], v);
    }
}

// ---------------------------------------------------------------------------
// K4: redundant pickA + level-B histogram (float4 stream). <<<256,512>>>
// ---------------------------------------------------------------------------
__global__ void __launch_bounds__(512) k_pickA_histB()
{
    __shared__ unsigned ssc[512];
    __shared__ unsigned sp[3];
    int t = threadIdx.x;
    if (t < 3) sp[t] = 0xFFFFFFFFu;

    unsigned loc[4], s = 0;
    #pragma unroll
    for (int k = 0; k < 4; k++) { loc[k] = g_hA[t*4 + k]; s += loc[k]; }
    ssc[t] = s;
    __syncthreads();
    #pragma unroll
    for (int off = 1; off < 512; off <<= 1) {
        unsigned v = ssc[t];
        unsigned a = (t >= off) ? ssc[t - off] : 0u;
        __syncthreads();
        ssc[t] = v + a;
        __syncthreads();
    }
    unsigned inc = ssc[t], exc = inc - s;
    unsigned n = ssc[511];
    if (t == 0) g_n = n;
    if (!n) return;

    unsigned r[3];
    r[0] = (n/4 > 0u) ? (n/4 - 1u) : 0u;
    r[1] = n/2;
    unsigned q3i = (unsigned)((3ull * n) / 4ull);
    if (q3i > n - 1u) q3i = n - 1u;
    r[2] = q3i;
    #pragma unroll
    for (int st = 0; st < 3; st++) {
        if (s && exc <= r[st] && r[st] < inc) {
            unsigned cum = exc;
            #pragma unroll
            for (int k = 0; k < 4; k++) {
                if (cum + loc[k] > r[st]) {
                    sp[st] = (unsigned)(t*4 + k);
                    g_pA[st] = sp[st];
                    g_rA[st] = r[st] - cum;
                    break;
                }
                cum += loc[k];
            }
        }
    }
    __syncthreads();

    unsigned p0 = sp[0], p1 = sp[1], p2 = sp[2];
    unsigned T  = g_bwoff[NB2];
    unsigned T4 = T >> 2;
    const float4* buf4 = (const float4*)g_bufw;
    unsigned stride = gridDim.x * blockDim.x;
    unsigned gt = blockIdx.x * blockDim.x + t;
    for (unsigned i4 = gt; i4 < T4; i4 += stride) {
        float4 v4 = buf4[i4];
        #pragma unroll
        for (int c = 0; c < 4; c++) {
            unsigned bits = __float_as_uint(c == 0 ? v4.x : c == 1 ? v4.y : c == 2 ? v4.z : v4.w);
            unsigned a11 = bits >> 21, m11 = (bits >> 10) & 2047u;
            if (a11 == p0) atomicAdd(&g_hB[m11],        1u);
            if (a11 == p1) atomicAdd(&g_hB[2048 + m11], 1u);
            if (a11 == p2) atomicAdd(&g_hB[4096 + m11], 1u);
        }
    }
    for (unsigned idx = (T4 << 2) + gt; idx < T; idx += stride) {
        unsigned bits = __float_as_uint(g_bufw[idx]);
        unsigned a11 = bits >> 21, m11 = (bits >> 10) & 2047u;
        if (a11 == p0) atomicAdd(&g_hB[m11],        1u);
        if (a11 == p1) atomicAdd(&g_hB[2048 + m11], 1u);
        if (a11 == p2) atomicAdd(&g_hB[4096 + m11], 1u);
    }
}

// ---------------------------------------------------------------------------
// K5: redundant pickB + level-C histogram (float4 stream). <<<256,512>>>
// ---------------------------------------------------------------------------
__global__ void __launch_bounds__(512) k_pickB_histC()
{
    __shared__ unsigned ssc[512];
    __shared__ unsigned spf[3];
    int t = threadIdx.x;
    if (t < 3) spf[t] = 0xFFFFFFFFu;
    unsigned n = g_n;
    if (!n) return;

    for (int st = 0; st < 3; st++) {
        unsigned rA = g_rA[st];
        unsigned pA = g_pA[st];
        unsigned loc[4], s = 0;
        #pragma unroll
        for (int k = 0; k < 4; k++) { loc[k] = g_hB[st*2048 + t*4 + k]; s += loc[k]; }
        ssc[t] = s;
        __syncthreads();
        #pragma unroll
        for (int off = 1; off < 512; off <<= 1) {
            unsigned v = ssc[t];
            unsigned a = (t >= off) ? ssc[t - off] : 0u;
            __syncthreads();
            ssc[t] = v + a;
            __syncthreads();
        }
        unsigned inc = ssc[t], exc = inc - s;
        if (s && exc <= rA && rA < inc) {
            unsigned cum = exc;
            #pragma unroll
            for (int k = 0; k < 4; k++) {
                if (cum + loc[k] > rA) {
                    unsigned pb = (unsigned)(t*4 + k);
                    g_pB[st] = pb;
                    g_rB[st] = rA - cum;
                    spf[st]  = (pA << 11) | pb;
                    break;
                }
                cum += loc[k];
            }
        }
        __syncthreads();
    }

    unsigned p0 = spf[0], p1 = spf[1], p2 = spf[2];
    unsigned T  = g_bwoff[NB2];
    unsigned T4 = T >> 2;
    const float4* buf4 = (const float4*)g_bufw;
    unsigned stride = gridDim.x * blockDim.x;
    unsigned gt = blockIdx.x * blockDim.x + t;
    for (unsigned i4 = gt; i4 < T4; i4 += stride) {
        float4 v4 = buf4[i4];
        #pragma unroll
        for (int c = 0; c < 4; c++) {
            unsigned bits = __float_as_uint(c == 0 ? v4.x : c == 1 ? v4.y : c == 2 ? v4.z : v4.w);
            unsigned ab22 = bits >> 10, l10 = bits & 1023u;
            if (ab22 == p0) atomicAdd(&g_hC[l10],        1u);
            if (ab22 == p1) atomicAdd(&g_hC[1024 + l10], 1u);
            if (ab22 == p2) atomicAdd(&g_hC[2048 + l10], 1u);
        }
    }
    for (unsigned idx = (T4 << 2) + gt; idx < T; idx += stride) {
        unsigned bits = __float_as_uint(g_bufw[idx]);
        unsigned ab22 = bits >> 10, l10 = bits & 1023u;
        if (ab22 == p0) atomicAdd(&g_hC[l10],        1u);
        if (ab22 == p1) atomicAdd(&g_hC[1024 + l10], 1u);
        if (ab22 == p2) atomicAdd(&g_hC[2048 + l10], 1u);
    }
}

// ---------------------------------------------------------------------------
// K6: redundant pickC -> q1/mu/q3, hinge loss (float4 stream), finalize.
//     <<<256,512>>>
// ---------------------------------------------------------------------------
__global__ void __launch_bounds__(512) k_loss(float* __restrict__ out)
{
    __shared__ unsigned ssc[512];
    __shared__ float    sq[3];
    int t = threadIdx.x;
    if (t < 3) sq[t] = 0.f;
    unsigned n = g_n;

    double acc = 0.0;
    if (n) {
        for (int st = 0; st < 3; st++) {
            unsigned rB = g_rB[st];
            unsigned pA = g_pA[st], pB = g_pB[st];
            unsigned loc[2], s = 0;
            #pragma unroll
            for (int k = 0; k < 2; k++) { loc[k] = g_hC[st*1024 + t*2 + k]; s += loc[k]; }
            ssc[t] = s;
            __syncthreads();
            #pragma unroll
            for (int off = 1; off < 512; off <<= 1) {
                unsigned v = ssc[t];
                unsigned a = (t >= off) ? ssc[t - off] : 0u;
                __syncthreads();
                ssc[t] = v + a;
                __syncthreads();
            }
            unsigned inc = ssc[t], exc = inc - s;
            if (s && exc <= rB && rB < inc) {
                unsigned cum = exc;
                #pragma unroll
                for (int k = 0; k < 2; k++) {
                    if (cum + loc[k] > rB) {
                        sq[st] = __uint_as_float((pA << 21) | (pB << 10) | (unsigned)(t*2 + k));
                        break;
                    }
                    cum += loc[k];
                }
            }
            __syncthreads();
        }
        float mu = sq[1];
        float margin = fmaxf(sq[2] - sq[0], 1e-6f) * 0.75f;   // iqr * 0.5 * 1.5

        unsigned T  = g_bwoff[NB2];
        unsigned T4 = T >> 2;
        const float4* buf4 = (const float4*)g_bufw;
        unsigned stride = gridDim.x * blockDim.x;
        unsigned gt = blockIdx.x * blockDim.x + t;
        for (unsigned i4 = gt; i4 < T4; i4 += stride) {
            float4 v4 = buf4[i4];
            #pragma unroll
            for (int c = 0; c < 4; c++) {
                float d = (c == 0 ? v4.x : c == 1 ? v4.y : c == 2 ? v4.z : v4.w);
                if (__float_as_uint(d) < INF_BITS) {
                    float h = fabsf(d - mu) - margin;
                    if (h > 0.f) acc += (double)h;
                }
            }
        }
        for (unsigned idx = (T4 << 2) + gt; idx < T; idx += stride) {
            float d = g_bufw[idx];
            if (__float_as_uint(d) < INF_BITS) {
                float h = fabsf(d - mu) - margin;
                if (h > 0.f) acc += (double)h;
            }
        }
    }

    for (int o = 16; o; o >>= 1) acc += __shfl_down_sync(0xFFFFFFFFu, acc, o);
    __shared__ double shs[16];
    if ((t & 31) == 0) shs[t >> 5] = acc;
    __syncthreads();
    if (t < 32) {
        double v = (t < 16) ? shs[t] : 0.0;
        for (int o = 8; o; o >>= 1) v += __shfl_down_sync(0xFFFFFFFFu, v, o);
        if (t == 0 && v != 0.0) atomicAdd(&g_sum, v);
    }
    __shared__ bool last;
    if (t == 0) {
        __threadfence();
        last = (atomicAdd(&g_done, 1u) == gridDim.x - 1);
    }
    __syncthreads();
    if (last && t == 0) {
        __threadfence();
        double denom = (double)(n > 0u ? n : 1u);
        out[0] = (float)(*(volatile double*)&g_sum / denom);
    }
}

// ---------------------------------------------------------------------------
extern "C" void kernel_launch(void* const* d_in, const int* in_sizes, int n_in,
                              void* d_out, int out_size)
{
    const float* pos  = (const float*)d_in[0];   // node_positions (B*N, 2)
    // d_in[1] = adjacency: unused
    const int*   eidx = (const int*)d_in[2];     // edge_index (2, E)
    float* out = (float*)d_out;

    int E = in_sizes[2] / 2;
    if (E > EMAX) E = EMAX;

    k_setup<<<32, 256>>>(pos, eidx, E);
    k_fill<<<16, 256>>>(E);
    k_enum<<<256, 512>>>(E);
    k_pickA_histB<<<256, 512>>>();
    k_pickB_histC<<<256, 512>>>();
    k_loss<<<256, 512>>>(out);
}

// round 12
// speedup vs baseline: 4.0444x; 1.3833x over previous
#include <cuda_runtime.h>
#include <math.h>

#define EMAX 4096
#define NB2  256
#define W    8
#define CAPW (EMAX*EMAX/2 + EMAX)     /* one-sided window-slot buffer */
#define PI_F   3.14159274101257324f
#define THR_F  0.08726646259971647f
#define BSCALE 81.48733086305042f     /* 256/pi */
#define INF_BITS 0x7F800000u

// ---- device scratch (no allocations allowed) ----
__device__ float4   g_i4[EMAX];        // (ang, nx, ny, c) by original edge idx
__device__ float2   g_mid[EMAX];
__device__ int      g_bine[EMAX];
__device__ unsigned g_bcnt[NB2], g_bcur[NB2];
__device__ unsigned g_boff[NB2 + 1];
__device__ unsigned g_Bb[NB2 + 1];     // one-sided slot-base per bucket (scan of S_b)
__device__ float4   g_q4[EMAX];        // bucket-order: (ang, mx, my, bitcast(orig idx))
__device__ float4   g_l4[EMAX];        // bucket-order: (nx, ny, c, unused)
__device__ __align__(16) float g_bufw[CAPW];  // window slots: dist or +inf
__device__ unsigned g_hA[2048];        // float bits [21..31]
__device__ unsigned g_hB[3 * 2048];    // bits [10..20] per rank
__device__ unsigned g_hC[3 * 1024];    // bits [0..9]  per rank
__device__ unsigned g_n;
__device__ unsigned g_pA[3], g_rA[3];
__device__ unsigned g_pB[3], g_rB[3];
__device__ unsigned g_done;
__device__ double   g_sum;

// ---------------------------------------------------------------------------
// K1: zero scratch + per-edge geometry + bucket counts.  <<<32,256>>>
// ---------------------------------------------------------------------------
__global__ void k_setup(const float* __restrict__ pos, const int* __restrict__ eidx, int E)
{
    int gtid = blockIdx.x * blockDim.x + threadIdx.x;
    int nt   = gridDim.x * blockDim.x;
    for (int k = gtid; k < 2048;   k += nt) g_hA[k] = 0u;
    for (int k = gtid; k < 3*2048; k += nt) g_hB[k] = 0u;
    for (int k = gtid; k < 3*1024; k += nt) g_hC[k] = 0u;
    if (gtid < NB2) { g_bcnt[gtid] = 0u; g_bcur[gtid] = 0u; }
    if (gtid == 0)  { g_sum = 0.0; g_done = 0u; g_n = 0u; }

    if (gtid < E) {
        int e = gtid;
        int s = eidx[e];
        int d = eidx[E + e];
        float sx = pos[2*s], sy = pos[2*s+1];
        float dx = pos[2*d], dy = pos[2*d+1];
        float vx = dx - sx, vy = dy - sy;
        float len = fmaxf(sqrtf(vx*vx + vy*vy), 1e-8f);
        float ux = vx / len, uy = vy / len;
        float a = atan2f(uy, ux);
        a = fmodf(a, PI_F);
        if (a < 0.f) a += PI_F;
        float nx = -uy, ny = ux;
        g_i4[e]  = make_float4(a, nx, ny, sx*nx + sy*ny);
        g_mid[e] = make_float2((sx + dx) * 0.5f, (sy + dy) * 0.5f);
        int b = (int)(a * BSCALE);
        if (b >= NB2) b = NB2 - 1;
        if (b < 0)    b = 0;
        g_bine[e] = b;
        atomicAdd(&g_bcnt[b], 1u);
    }
}

// ---------------------------------------------------------------------------
// K2: redundant per-block scans (bucket offsets + one-sided slot bases) +
//     bucket scatter.  <<<16,256>>>
// ---------------------------------------------------------------------------
__global__ void k_fill(int E)
{
    __shared__ unsigned sOff[NB2 + 1];
    __shared__ unsigned ssc[NB2];
    int t = threadIdx.x;

    unsigned c = g_bcnt[t];
    ssc[t] = c;
    __syncthreads();
    #pragma unroll
    for (int off = 1; off < NB2; off <<= 1) {
        unsigned v = ssc[t];
        unsigned a = (t >= off) ? ssc[t - off] : 0u;
        __syncthreads();
        ssc[t] = v + a;
        __syncthreads();
    }
    unsigned exc = ssc[t] - c;
    sOff[t] = exc;
    g_boff[t] = exc;
    if (t == NB2 - 1) { sOff[NB2] = ssc[NB2 - 1]; g_boff[NB2] = ssc[NB2 - 1]; }
    __syncthreads();

    // one-sided per-bucket slot totals:
    // cnt(s) = (U_b - s - 1) + X_b  for s in [o_b, o_b + c_b)
    {
        int b = t;
        unsigned o = sOff[b];
        unsigned U = sOff[(b + 9 <= NB2) ? (b + 9) : NB2];
        unsigned X = (b <= 7) ? (sOff[NB2] - sOff[b + 248]) : 0u;
        // S_b = c*(U-1+X) - c*o - c(c-1)/2
        unsigned S = c * (U - 1u + X) - c * o - (c * (c - 1u)) / 2u;
        ssc[t] = S;
        __syncthreads();
        #pragma unroll
        for (int off = 1; off < NB2; off <<= 1) {
            unsigned v = ssc[t];
            unsigned a = (t >= off) ? ssc[t - off] : 0u;
            __syncthreads();
            ssc[t] = v + a;
            __syncthreads();
        }
        g_Bb[t] = ssc[t] - S;
        if (t == NB2 - 1) g_Bb[NB2] = ssc[NB2 - 1];
    }
    __syncthreads();

    int e = blockIdx.x * blockDim.x + t;
    if (e < E) {
        int b = g_bine[e];
        unsigned slot = sOff[b] + atomicAdd(&g_bcur[b], 1u);
        float4 f = g_i4[e];
        float2 m = g_mid[e];
        g_q4[slot] = make_float4(f.x, m.x, m.y, __int_as_float(e));
        g_l4[slot] = make_float4(f.y, f.z, f.w, 0.f);
    }
}

// ---------------------------------------------------------------------------
// K3: ONE-SIDED enumeration — slot s scans window slots k > s only.
//     Deterministic closed-form bases; shared 2048-bin level-A hist.
//     <<<256,512>>>
// ---------------------------------------------------------------------------
__global__ void __launch_bounds__(512) k_enum(int E)
{
    __shared__ unsigned sb[NB2 + 1];
    __shared__ unsigned sB[NB2];
    __shared__ unsigned sh[2048];
    int t = threadIdx.x;
    for (int k = t; k <= NB2; k += 512) sb[k] = g_boff[k];
    for (int k = t; k < NB2;  k += 512) sB[k] = g_Bb[k];
    for (int k = t; k < 2048; k += 512) sh[k] = 0u;
    __syncthreads();

    int gw   = (blockIdx.x * blockDim.x + t) >> 5;
    int lane = t & 31;
    int nw   = (gridDim.x * blockDim.x) >> 5;

    for (int s = gw; s < E; s += nw) {
        float4 qs = g_q4[s];
        int u = __float_as_int(qs.w);
        float au = qs.x, mxu = qs.y, myu = qs.z;
        float4 lu = g_l4[s];
        float nxu = lu.x, nyu = lu.y, cu = lu.z;
        int b = g_bine[u];

        int o = (int)sb[b];
        int U = (int)sb[(b + 9 <= NB2) ? (b + 9) : NB2];
        int X = (b <= 7) ? (int)(sb[NB2] - sb[b + 248]) : 0;

        // base(s) = B_b + (s-o)*(U-1+X) - (o+s-1)*(s-o)/2
        int so = s - o;
        unsigned base = sB[b] + (unsigned)(so * (U - 1 + X)) - (unsigned)(((o + s - 1) * so) / 2);
        int cnt_f = U - s - 1;

        // forward: k in (s, U)
        for (int k = s + 1 + lane; k < U; k += 32) {
            float4 q = g_q4[k];
            float da   = fabsf(au - q.x);
            float circ = fminf(da, PI_F - da);
            float val  = __uint_as_float(INF_BITS);
            if (circ <= THR_F) {                     // exact reference mask
                int ov = __float_as_int(q.w);
                if (u < ov) {
                    val = fabsf(fmaf(nxu, q.y, fmaf(nyu, q.z, -cu)));
                } else {
                    float4 lv = g_l4[k];
                    val = fabsf(fmaf(lv.x, mxu, fmaf(lv.y, myu, -lv.z)));
                }
                atomicAdd(&sh[__float_as_uint(val) >> 21], 1u);
            }
            g_bufw[base + (unsigned)(k - s - 1)] = val;
        }
        // wrap block (b <= 7): k in [sb[b+248], sb[256]) — all k > s
        if (X > 0) {
            int ws = (int)sb[b + 248];
            int we = (int)sb[NB2];
            for (int k = ws + lane; k < we; k += 32) {
                float4 q = g_q4[k];
                float da   = fabsf(au - q.x);
                float circ = fminf(da, PI_F - da);
                float val  = __uint_as_float(INF_BITS);
                if (circ <= THR_F) {
                    int ov = __float_as_int(q.w);
                    if (u < ov) {
                        val = fabsf(fmaf(nxu, q.y, fmaf(nyu, q.z, -cu)));
                    } else {
                        float4 lv = g_l4[k];
                        val = fabsf(fmaf(lv.x, mxu, fmaf(lv.y, myu, -lv.z)));
                    }
                    atomicAdd(&sh[__float_as_uint(val) >> 21], 1u);
                }
                g_bufw[base + (unsigned)(cnt_f + (k - ws))] = val;
            }
        }
    }
    __syncthreads();
    for (int k = t; k < 2048; k += 512) {
        unsigned v = sh[k];
        if (v) atomicAdd(&g_hA[k], v);
    }
}

// ---------------------------------------------------------------------------
// K4: redundant pickA + level-B histogram (float4 stream). <<<256,512>>>
// ---------------------------------------------------------------------------
__global__ void __launch_bounds__(512) k_pickA_histB()
{
    __shared__ unsigned ssc[512];
    __shared__ unsigned sp[3];
    int t = threadIdx.x;
    if (t < 3) sp[t] = 0xFFFFFFFFu;

    unsigned loc[4], s = 0;
    #pragma unroll
    for (int k = 0; k < 4; k++) { loc[k] = g_hA[t*4 + k]; s += loc[k]; }
    ssc[t] = s;
    __syncthreads();
    #pragma unroll
    for (int off = 1; off < 512; off <<= 1) {
        unsigned v = ssc[t];
        unsigned a = (t >= off) ? ssc[t - off] : 0u;
        __syncthreads();
        ssc[t] = v + a;
        __syncthreads();
    }
    unsigned inc = ssc[t], exc = inc - s;
    unsigned n = ssc[511];
    if (t == 0) g_n = n;
    if (!n) return;

    unsigned r[3];
    r[0] = (n/4 > 0u) ? (n/4 - 1u) : 0u;
    r[1] = n/2;
    unsigned q3i = (unsigned)((3ull * n) / 4ull);
    if (q3i > n - 1u) q3i = n - 1u;
    r[2] = q3i;
    #pragma unroll
    for (int st = 0; st < 3; st++) {
        if (s && exc <= r[st] && r[st] < inc) {
            unsigned cum = exc;
            #pragma unroll
            for (int k = 0; k < 4; k++) {
                if (cum + loc[k] > r[st]) {
                    sp[st] = (unsigned)(t*4 + k);
                    g_pA[st] = sp[st];
                    g_rA[st] = r[st] - cum;
                    break;
                }
                cum += loc[k];
            }
        }
    }
    __syncthreads();

    unsigned p0 = sp[0], p1 = sp[1], p2 = sp[2];
    unsigned T  = g_Bb[NB2];
    unsigned T4 = T >> 2;
    const float4* buf4 = (const float4*)g_bufw;
    unsigned stride = gridDim.x * blockDim.x;
    unsigned gt = blockIdx.x * blockDim.x + t;
    for (unsigned i4 = gt; i4 < T4; i4 += stride) {
        float4 v4 = buf4[i4];
        #pragma unroll
        for (int c = 0; c < 4; c++) {
            unsigned bits = __float_as_uint(c == 0 ? v4.x : c == 1 ? v4.y : c == 2 ? v4.z : v4.w);
            unsigned a11 = bits >> 21, m11 = (bits >> 10) & 2047u;
            if (a11 == p0) atomicAdd(&g_hB[m11],        1u);
            if (a11 == p1) atomicAdd(&g_hB[2048 + m11], 1u);
            if (a11 == p2) atomicAdd(&g_hB[4096 + m11], 1u);
        }
    }
    for (unsigned idx = (T4 << 2) + gt; idx < T; idx += stride) {
        unsigned bits = __float_as_uint(g_bufw[idx]);
        unsigned a11 = bits >> 21, m11 = (bits >> 10) & 2047u;
        if (a11 == p0) atomicAdd(&g_hB[m11],        1u);
        if (a11 == p1) atomicAdd(&g_hB[2048 + m11], 1u);
        if (a11 == p2) atomicAdd(&g_hB[4096 + m11], 1u);
    }
}

// ---------------------------------------------------------------------------
// K5: redundant pickB + level-C histogram (float4 stream). <<<256,512>>>
// ---------------------------------------------------------------------------
__global__ void __launch_bounds__(512) k_pickB_histC()
{
    __shared__ unsigned ssc[512];
    __shared__ unsigned spf[3];
    int t = threadIdx.x;
    if (t < 3) spf[t] = 0xFFFFFFFFu;
    unsigned n = g_n;
    if (!n) return;

    for (int st = 0; st < 3; st++) {
        unsigned rA = g_rA[st];
        unsigned pA = g_pA[st];
        unsigned loc[4], s = 0;
        #pragma unroll
        for (int k = 0; k < 4; k++) { loc[k] = g_hB[st*2048 + t*4 + k]; s += loc[k]; }
        ssc[t] = s;
        __syncthreads();
        #pragma unroll
        for (int off = 1; off < 512; off <<= 1) {
            unsigned v = ssc[t];
            unsigned a = (t >= off) ? ssc[t - off] : 0u;
            __syncthreads();
            ssc[t] = v + a;
            __syncthreads();
        }
        unsigned inc = ssc[t], exc = inc - s;
        if (s && exc <= rA && rA < inc) {
            unsigned cum = exc;
            #pragma unroll
            for (int k = 0; k < 4; k++) {
                if (cum + loc[k] > rA) {
                    unsigned pb = (unsigned)(t*4 + k);
                    g_pB[st] = pb;
                    g_rB[st] = rA - cum;
                    spf[st]  = (pA << 11) | pb;
                    break;
                }
                cum += loc[k];
            }
        }
        __syncthreads();
    }

    unsigned p0 = spf[0], p1 = spf[1], p2 = spf[2];
    unsigned T  = g_Bb[NB2];
    unsigned T4 = T >> 2;
    const float4* buf4 = (const float4*)g_bufw;
    unsigned stride = gridDim.x * blockDim.x;
    unsigned gt = blockIdx.x * blockDim.x + t;
    for (unsigned i4 = gt; i4 < T4; i4 += stride) {
        float4 v4 = buf4[i4];
        #pragma unroll
        for (int c = 0; c < 4; c++) {
            unsigned bits = __float_as_uint(c == 0 ? v4.x : c == 1 ? v4.y : c == 2 ? v4.z : v4.w);
            unsigned ab22 = bits >> 10, l10 = bits & 1023u;
            if (ab22 == p0) atomicAdd(&g_hC[l10],        1u);
            if (ab22 == p1) atomicAdd(&g_hC[1024 + l10], 1u);
            if (ab22 == p2) atomicAdd(&g_hC[2048 + l10], 1u);
        }
    }
    for (unsigned idx = (T4 << 2) + gt; idx < T; idx += stride) {
        unsigned bits = __float_as_uint(g_bufw[idx]);
        unsigned ab22 = bits >> 10, l10 = bits & 1023u;
        if (ab22 == p0) atomicAdd(&g_hC[l10],        1u);
        if (ab22 == p1) atomicAdd(&g_hC[1024 + l10], 1u);
        if (ab22 == p2) atomicAdd(&g_hC[2048 + l10], 1u);
    }
}

// ---------------------------------------------------------------------------
// K6: redundant pickC -> q1/mu/q3, hinge loss (float4 stream), finalize.
//     <<<256,512>>>
// ---------------------------------------------------------------------------
__global__ void __launch_bounds__(512) k_loss(float* __restrict__ out)
{
    __shared__ unsigned ssc[512];
    __shared__ float    sq[3];
    int t = threadIdx.x;
    if (t < 3) sq[t] = 0.f;
    unsigned n = g_n;

    double acc = 0.0;
    if (n) {
        for (int st = 0; st < 3; st++) {
            unsigned rB = g_rB[st];
            unsigned pA = g_pA[st], pB = g_pB[st];
            unsigned loc[2], s = 0;
            #pragma unroll
            for (int k = 0; k < 2; k++) { loc[k] = g_hC[st*1024 + t*2 + k]; s += loc[k]; }
            ssc[t] = s;
            __syncthreads();
            #pragma unroll
            for (int off = 1; off < 512; off <<= 1) {
                unsigned v = ssc[t];
                unsigned a = (t >= off) ? ssc[t - off] : 0u;
                __syncthreads();
                ssc[t] = v + a;
                __syncthreads();
            }
            unsigned inc = ssc[t], exc = inc - s;
            if (s && exc <= rB && rB < inc) {
                unsigned cum = exc;
                #pragma unroll
                for (int k = 0; k < 2; k++) {
                    if (cum + loc[k] > rB) {
                        sq[st] = __uint_as_float((pA << 21) | (pB << 10) | (unsigned)(t*2 + k));
                        break;
                    }
                    cum += loc[k];
                }
            }
            __syncthreads();
        }
        float mu = sq[1];
        float margin = fmaxf(sq[2] - sq[0], 1e-6f) * 0.75f;   // iqr * 0.5 * 1.5

        unsigned T  = g_Bb[NB2];
        unsigned T4 = T >> 2;
        const float4* buf4 = (const float4*)g_bufw;
        unsigned stride = gridDim.x * blockDim.x;
        unsigned gt = blockIdx.x * blockDim.x + t;
        for (unsigned i4 = gt; i4 < T4; i4 += stride) {
            float4 v4 = buf4[i4];
            #pragma unroll
            for (int c = 0; c < 4; c++) {
                float d = (c == 0 ? v4.x : c == 1 ? v4.y : c == 2 ? v4.z : v4.w);
                if (__float_as_uint(d) < INF_BITS) {
                    float h = fabsf(d - mu) - margin;
                    if (h > 0.f) acc += (double)h;
                }
            }
        }
        for (unsigned idx = (T4 << 2) + gt; idx < T; idx += stride) {
            float d = g_bufw[idx];
            if (__float_as_uint(d) < INF_BITS) {
                float h = fabsf(d - mu) - margin;
                if (h > 0.f) acc += (double)h;
            }
        }
    }

    for (int o = 16; o; o >>= 1) acc += __shfl_down_sync(0xFFFFFFFFu, acc, o);
    __shared__ double shs[16];
    if ((t & 31) == 0) shs[t >> 5] = acc;
    __syncthreads();
    if (t < 32) {
        double v = (t < 16) ? shs[t] : 0.0;
        for (int o = 8; o; o >>= 1) v += __shfl_down_sync(0xFFFFFFFFu, v, o);
        if (t == 0 && v != 0.0) atomicAdd(&g_sum, v);
    }
    __shared__ bool last;
    if (t == 0) {
        __threadfence();
        last = (atomicAdd(&g_done, 1u) == gridDim.x - 1);
    }
    __syncthreads();
    if (last && t == 0) {
        __threadfence();
        double denom = (double)(n > 0u ? n : 1u);
        out[0] = (float)(*(volatile double*)&g_sum / denom);
    }
}

// ---------------------------------------------------------------------------
extern "C" void kernel_launch(void* const* d_in, const int* in_sizes, int n_in,
                              void* d_out, int out_size)
{
    const float* pos  = (const float*)d_in[0];   // node_positions (B*N, 2)
    // d_in[1] = adjacency: unused
    const int*   eidx = (const int*)d_in[2];     // edge_index (2, E)
    float* out = (float*)d_out;

    int E = in_sizes[2] / 2;
    if (E > EMAX) E = EMAX;

    k_setup<<<32, 256>>>(pos, eidx, E);
    k_fill<<<16, 256>>>(E);
    k_enum<<<256, 512>>>(E);
    k_pickA_histB<<<256, 512>>>();
    k_pickB_histC<<<256, 512>>>();
    k_loss<<<256, 512>>>(out);
}

// round 13
// speedup vs baseline: 4.3435x; 1.0740x over previous
#include <cuda_runtime.h>
#include <math.h>

#define EMAX 4096
#define NB2  256
#define W    8
#define CAPW (EMAX*EMAX/2 + EMAX)     /* one-sided window-slot buffer */
#define PI_F   3.14159274101257324f
#define THR_F  0.08726646259971647f
#define BSCALE 81.48733086305042f     /* 256/pi */
#define INF_BITS 0x7F800000u
#define SELGRID 256

// ---- device scratch (no allocations allowed) ----
__device__ float4   g_i4[EMAX];        // (ang, nx, ny, c) by original edge idx
__device__ float2   g_mid[EMAX];
__device__ int      g_bine[EMAX];
__device__ unsigned g_bcnt[NB2], g_bcur[NB2];
__device__ unsigned g_boff[NB2 + 1];
__device__ unsigned g_Bb[NB2 + 1];     // one-sided slot-base per bucket
__device__ float4   g_q4[EMAX];        // bucket-order: (ang, mx, my, bitcast(orig idx))
__device__ float4   g_l4[EMAX];        // bucket-order: (nx, ny, c, unused)
__device__ __align__(16) float g_bufw[CAPW];  // window slots: dist or +inf
__device__ unsigned g_hA[2048];        // float bits [21..31]
__device__ unsigned g_hB[3 * 2048];    // bits [10..20] per rank
__device__ unsigned g_hC[3 * 1024];    // bits [0..9]  per rank
__device__ unsigned g_n;
__device__ unsigned g_pA[3], g_rA[3];
__device__ unsigned g_pB[3], g_rB[3];
__device__ unsigned g_done;
__device__ double   g_sum;
// monotone grid-barrier state (never reset; replay-safe)
__device__ unsigned g_arrive_v;
__device__ unsigned g_sense_v;

// ---------------------------------------------------------------------------
__device__ __forceinline__ void gsync(unsigned base, unsigned& bidx)
{
    __syncthreads();
    if (threadIdx.x == 0) {
        unsigned target = base + (++bidx);
        __threadfence();
        unsigned old = atomicAdd(&g_arrive_v, 1u);
        if (old + 1u == target * SELGRID) {
            __threadfence();
            *(volatile unsigned*)&g_sense_v = target;
        } else {
            while ((int)(*(volatile unsigned*)&g_sense_v - target) < 0)
                __nanosleep(64);
        }
        __threadfence();
    }
    __syncthreads();
}

// ---------------------------------------------------------------------------
// K1: zero scratch + per-edge geometry + bucket counts.  <<<32,256>>>
// ---------------------------------------------------------------------------
__global__ void k_setup(const float* __restrict__ pos, const int* __restrict__ eidx, int E)
{
    int gtid = blockIdx.x * blockDim.x + threadIdx.x;
    int nt   = gridDim.x * blockDim.x;
    for (int k = gtid; k < 2048;   k += nt) g_hA[k] = 0u;
    for (int k = gtid; k < 3*2048; k += nt) g_hB[k] = 0u;
    for (int k = gtid; k < 3*1024; k += nt) g_hC[k] = 0u;
    if (gtid < NB2) { g_bcnt[gtid] = 0u; g_bcur[gtid] = 0u; }
    if (gtid == 0)  { g_sum = 0.0; g_done = 0u; g_n = 0u; }

    if (gtid < E) {
        int e = gtid;
        int s = eidx[e];
        int d = eidx[E + e];
        float sx = pos[2*s], sy = pos[2*s+1];
        float dx = pos[2*d], dy = pos[2*d+1];
        float vx = dx - sx, vy = dy - sy;
        float len = fmaxf(sqrtf(vx*vx + vy*vy), 1e-8f);
        float ux = vx / len, uy = vy / len;
        float a = atan2f(uy, ux);
        a = fmodf(a, PI_F);
        if (a < 0.f) a += PI_F;
        float nx = -uy, ny = ux;
        g_i4[e]  = make_float4(a, nx, ny, sx*nx + sy*ny);
        g_mid[e] = make_float2((sx + dx) * 0.5f, (sy + dy) * 0.5f);
        int b = (int)(a * BSCALE);
        if (b >= NB2) b = NB2 - 1;
        if (b < 0)    b = 0;
        g_bine[e] = b;
        atomicAdd(&g_bcnt[b], 1u);
    }
}

// ---------------------------------------------------------------------------
// K2: redundant per-block scans (bucket offsets + one-sided slot bases) +
//     bucket scatter.  <<<16,256>>>
// ---------------------------------------------------------------------------
__global__ void k_fill(int E)
{
    __shared__ unsigned sOff[NB2 + 1];
    __shared__ unsigned ssc[NB2];
    int t = threadIdx.x;

    unsigned c = g_bcnt[t];
    ssc[t] = c;
    __syncthreads();
    #pragma unroll
    for (int off = 1; off < NB2; off <<= 1) {
        unsigned v = ssc[t];
        unsigned a = (t >= off) ? ssc[t - off] : 0u;
        __syncthreads();
        ssc[t] = v + a;
        __syncthreads();
    }
    unsigned exc = ssc[t] - c;
    sOff[t] = exc;
    g_boff[t] = exc;
    if (t == NB2 - 1) { sOff[NB2] = ssc[NB2 - 1]; g_boff[NB2] = ssc[NB2 - 1]; }
    __syncthreads();

    {
        int b = t;
        unsigned o = sOff[b];
        unsigned U = sOff[(b + 9 <= NB2) ? (b + 9) : NB2];
        unsigned X = (b <= 7) ? (sOff[NB2] - sOff[b + 248]) : 0u;
        unsigned S = c * (U - 1u + X) - c * o - (c * (c - 1u)) / 2u;
        ssc[t] = S;
        __syncthreads();
        #pragma unroll
        for (int off = 1; off < NB2; off <<= 1) {
            unsigned v = ssc[t];
            unsigned a = (t >= off) ? ssc[t - off] : 0u;
            __syncthreads();
            ssc[t] = v + a;
            __syncthreads();
        }
        g_Bb[t] = ssc[t] - S;
        if (t == NB2 - 1) g_Bb[NB2] = ssc[NB2 - 1];
    }
    __syncthreads();

    int e = blockIdx.x * blockDim.x + t;
    if (e < E) {
        int b = g_bine[e];
        unsigned slot = sOff[b] + atomicAdd(&g_bcur[b], 1u);
        float4 f = g_i4[e];
        float2 m = g_mid[e];
        g_q4[slot] = make_float4(f.x, m.x, m.y, __int_as_float(e));
        g_l4[slot] = make_float4(f.y, f.z, f.w, 0.f);
    }
}

// ---------------------------------------------------------------------------
// K3: ONE-SIDED enumeration — slot s scans window slots k > s only.
//     Deterministic closed-form bases; shared 2048-bin level-A hist.
//     <<<256,512>>>
// ---------------------------------------------------------------------------
__global__ void __launch_bounds__(512) k_enum(int E)
{
    __shared__ unsigned sb[NB2 + 1];
    __shared__ unsigned sB[NB2];
    __shared__ unsigned sh[2048];
    int t = threadIdx.x;
    for (int k = t; k <= NB2; k += 512) sb[k] = g_boff[k];
    for (int k = t; k < NB2;  k += 512) sB[k] = g_Bb[k];
    for (int k = t; k < 2048; k += 512) sh[k] = 0u;
    __syncthreads();

    int gw   = (blockIdx.x * blockDim.x + t) >> 5;
    int lane = t & 31;
    int nw   = (gridDim.x * blockDim.x) >> 5;

    for (int s = gw; s < E; s += nw) {
        float4 qs = g_q4[s];
        int u = __float_as_int(qs.w);
        float au = qs.x, mxu = qs.y, myu = qs.z;
        float4 lu = g_l4[s];
        float nxu = lu.x, nyu = lu.y, cu = lu.z;
        int b = g_bine[u];

        int o = (int)sb[b];
        int U = (int)sb[(b + 9 <= NB2) ? (b + 9) : NB2];
        int X = (b <= 7) ? (int)(sb[NB2] - sb[b + 248]) : 0;

        int so = s - o;
        unsigned base = sB[b] + (unsigned)(so * (U - 1 + X)) - (unsigned)(((o + s - 1) * so) / 2);
        int cnt_f = U - s - 1;

        for (int k = s + 1 + lane; k < U; k += 32) {
            float4 q = g_q4[k];
            float da   = fabsf(au - q.x);
            float circ = fminf(da, PI_F - da);
            float val  = __uint_as_float(INF_BITS);
            if (circ <= THR_F) {                     // exact reference mask
                int ov = __float_as_int(q.w);
                if (u < ov) {
                    val = fabsf(fmaf(nxu, q.y, fmaf(nyu, q.z, -cu)));
                } else {
                    float4 lv = g_l4[k];
                    val = fabsf(fmaf(lv.x, mxu, fmaf(lv.y, myu, -lv.z)));
                }
                atomicAdd(&sh[__float_as_uint(val) >> 21], 1u);
            }
            g_bufw[base + (unsigned)(k - s - 1)] = val;
        }
        if (X > 0) {
            int ws = (int)sb[b + 248];
            int we = (int)sb[NB2];
            for (int k = ws + lane; k < we; k += 32) {
                float4 q = g_q4[k];
                float da   = fabsf(au - q.x);
                float circ = fminf(da, PI_F - da);
                float val  = __uint_as_float(INF_BITS);
                if (circ <= THR_F) {
                    int ov = __float_as_int(q.w);
                    if (u < ov) {
                        val = fabsf(fmaf(nxu, q.y, fmaf(nyu, q.z, -cu)));
                    } else {
                        float4 lv = g_l4[k];
                        val = fabsf(fmaf(lv.x, mxu, fmaf(lv.y, myu, -lv.z)));
                    }
                    atomicAdd(&sh[__float_as_uint(val) >> 21], 1u);
                }
                g_bufw[base + (unsigned)(cnt_f + (k - ws))] = val;
            }
        }
    }
    __syncthreads();
    for (int k = t; k < 2048; k += 512) {
        unsigned v = sh[k];
        if (v) atomicAdd(&g_hA[k], v);
    }
}

// ---------------------------------------------------------------------------
// K4 (FUSED): pickA + histB | gsync | pickB + histC | gsync | pickC + loss
//     + finalize.  <<<SELGRID,512>>>
// ---------------------------------------------------------------------------
__global__ void __launch_bounds__(512) k_select_loss(float* __restrict__ out)
{
    __shared__ unsigned ssc[512];
    __shared__ unsigned sp[3];
    __shared__ float    sq[3];
    __shared__ unsigned s_sense;
    int t = threadIdx.x;
    if (t == 0) s_sense = *(volatile unsigned*)&g_sense_v;
    if (t < 3) { sp[t] = 0xFFFFFFFFu; sq[t] = 0.f; }
    __syncthreads();
    const unsigned sbase = s_sense;
    unsigned bidx = 0;

    const unsigned T  = g_Bb[NB2];
    const unsigned T4 = T >> 2;
    const float4* buf4 = (const float4*)g_bufw;
    const unsigned stride = gridDim.x * blockDim.x;
    const unsigned gt = blockIdx.x * blockDim.x + t;

    // ---------------- phase 1: pickA + histB ----------------
    unsigned n;
    {
        unsigned loc[4], s = 0;
        #pragma unroll
        for (int k = 0; k < 4; k++) { loc[k] = g_hA[t*4 + k]; s += loc[k]; }
        ssc[t] = s;
        __syncthreads();
        #pragma unroll
        for (int off = 1; off < 512; off <<= 1) {
            unsigned v = ssc[t];
            unsigned a = (t >= off) ? ssc[t - off] : 0u;
            __syncthreads();
            ssc[t] = v + a;
            __syncthreads();
        }
        unsigned inc = ssc[t], exc = inc - s;
        n = ssc[511];
        if (t == 0) g_n = n;

        if (n) {
            unsigned r[3];
            r[0] = (n/4 > 0u) ? (n/4 - 1u) : 0u;
            r[1] = n/2;
            unsigned q3i = (unsigned)((3ull * n) / 4ull);
            if (q3i > n - 1u) q3i = n - 1u;
            r[2] = q3i;
            #pragma unroll
            for (int st = 0; st < 3; st++) {
                if (s && exc <= r[st] && r[st] < inc) {
                    unsigned cum = exc;
                    #pragma unroll
                    for (int k = 0; k < 4; k++) {
                        if (cum + loc[k] > r[st]) {
                            sp[st] = (unsigned)(t*4 + k);
                            g_pA[st] = sp[st];
                            g_rA[st] = r[st] - cum;
                            break;
                        }
                        cum += loc[k];
                    }
                }
            }
        }
        __syncthreads();

        if (n) {
            unsigned p0 = sp[0], p1 = sp[1], p2 = sp[2];
            for (unsigned i4 = gt; i4 < T4; i4 += stride) {
                float4 v4 = buf4[i4];
                #pragma unroll
                for (int c = 0; c < 4; c++) {
                    unsigned bits = __float_as_uint(c == 0 ? v4.x : c == 1 ? v4.y : c == 2 ? v4.z : v4.w);
                    unsigned a11 = bits >> 21, m11 = (bits >> 10) & 2047u;
                    if (a11 == p0) atomicAdd(&g_hB[m11],        1u);
                    if (a11 == p1) atomicAdd(&g_hB[2048 + m11], 1u);
                    if (a11 == p2) atomicAdd(&g_hB[4096 + m11], 1u);
                }
            }
            for (unsigned idx = (T4 << 2) + gt; idx < T; idx += stride) {
                unsigned bits = __float_as_uint(g_bufw[idx]);
                unsigned a11 = bits >> 21, m11 = (bits >> 10) & 2047u;
                if (a11 == p0) atomicAdd(&g_hB[m11],        1u);
                if (a11 == p1) atomicAdd(&g_hB[2048 + m11], 1u);
                if (a11 == p2) atomicAdd(&g_hB[4096 + m11], 1u);
            }
        }
    }
    gsync(sbase, bidx);                                    // B1

    // ---------------- phase 2: pickB + histC ----------------
    {
        __shared__ unsigned spf[3];
        if (t < 3) spf[t] = 0xFFFFFFFFu;
        if (n) {
            for (int st = 0; st < 3; st++) {
                unsigned rA = g_rA[st];
                unsigned pA = g_pA[st];
                unsigned loc[4], s = 0;
                #pragma unroll
                for (int k = 0; k < 4; k++) { loc[k] = g_hB[st*2048 + t*4 + k]; s += loc[k]; }
                ssc[t] = s;
                __syncthreads();
                #pragma unroll
                for (int off = 1; off < 512; off <<= 1) {
                    unsigned v = ssc[t];
                    unsigned a = (t >= off) ? ssc[t - off] : 0u;
                    __syncthreads();
                    ssc[t] = v + a;
                    __syncthreads();
                }
                unsigned inc = ssc[t], exc = inc - s;
                if (s && exc <= rA && rA < inc) {
                    unsigned cum = exc;
                    #pragma unroll
                    for (int k = 0; k < 4; k++) {
                        if (cum + loc[k] > rA) {
                            unsigned pb = (unsigned)(t*4 + k);
                            g_pB[st] = pb;
                            g_rB[st] = rA - cum;
                            spf[st]  = (pA << 11) | pb;
                            break;
                        }
                        cum += loc[k];
                    }
                }
                __syncthreads();
            }
            unsigned p0 = spf[0], p1 = spf[1], p2 = spf[2];
            for (unsigned i4 = gt; i4 < T4; i4 += stride) {
                float4 v4 = buf4[i4];
                #pragma unroll
                for (int c = 0; c < 4; c++) {
                    unsigned bits = __float_as_uint(c == 0 ? v4.x : c == 1 ? v4.y : c == 2 ? v4.z : v4.w);
                    unsigned ab22 = bits >> 10, l10 = bits & 1023u;
                    if (ab22 == p0) atomicAdd(&g_hC[l10],        1u);
                    if (ab22 == p1) atomicAdd(&g_hC[1024 + l10], 1u);
                    if (ab22 == p2) atomicAdd(&g_hC[2048 + l10], 1u);
                }
            }
            for (unsigned idx = (T4 << 2) + gt; idx < T; idx += stride) {
                unsigned bits = __float_as_uint(g_bufw[idx]);
                unsigned ab22 = bits >> 10, l10 = bits & 1023u;
                if (ab22 == p0) atomicAdd(&g_hC[l10],        1u);
                if (ab22 == p1) atomicAdd(&g_hC[1024 + l10], 1u);
                if (ab22 == p2) atomicAdd(&g_hC[2048 + l10], 1u);
            }
        }
    }
    gsync(sbase, bidx);                                    // B2

    // ---------------- phase 3: pickC + loss + finalize ----------------
    double acc = 0.0;
    if (n) {
        for (int st = 0; st < 3; st++) {
            unsigned rB = g_rB[st];
            unsigned pA = g_pA[st], pB = g_pB[st];
            unsigned loc[2], s = 0;
            #pragma unroll
            for (int k = 0; k < 2; k++) { loc[k] = g_hC[st*1024 + t*2 + k]; s += loc[k]; }
            ssc[t] = s;
            __syncthreads();
            #pragma unroll
            for (int off = 1; off < 512; off <<= 1) {
                unsigned v = ssc[t];
                unsigned a = (t >= off) ? ssc[t - off] : 0u;
                __syncthreads();
                ssc[t] = v + a;
                __syncthreads();
            }
            unsigned inc = ssc[t], exc = inc - s;
            if (s && exc <= rB && rB < inc) {
                unsigned cum = exc;
                #pragma unroll
                for (int k = 0; k < 2; k++) {
                    if (cum + loc[k] > rB) {
                        sq[st] = __uint_as_float((pA << 21) | (pB << 10) | (unsigned)(t*2 + k));
                        break;
                    }
                    cum += loc[k];
                }
            }
            __syncthreads();
        }
        float mu = sq[1];
        float margin = fmaxf(sq[2] - sq[0], 1e-6f) * 0.75f;   // iqr * 0.5 * 1.5

        for (unsigned i4 = gt; i4 < T4; i4 += stride) {
            float4 v4 = buf4[i4];
            #pragma unroll
            for (int c = 0; c < 4; c++) {
                float d = (c == 0 ? v4.x : c == 1 ? v4.y : c == 2 ? v4.z : v4.w);
                if (__float_as_uint(d) < INF_BITS) {
                    float h = fabsf(d - mu) - margin;
                    if (h > 0.f) acc += (double)h;
                }
            }
        }
        for (unsigned idx = (T4 << 2) + gt; idx < T; idx += stride) {
            float d = g_bufw[idx];
            if (__float_as_uint(d) < INF_BITS) {
                float h = fabsf(d - mu) - margin;
                if (h > 0.f) acc += (double)h;
            }
        }
    }

    for (int o = 16; o; o >>= 1) acc += __shfl_down_sync(0xFFFFFFFFu, acc, o);
    __shared__ double shs[16];
    if ((t & 31) == 0) shs[t >> 5] = acc;
    __syncthreads();
    if (t < 32) {
        double v = (t < 16) ? shs[t] : 0.0;
        for (int o = 8; o; o >>= 1) v += __shfl_down_sync(0xFFFFFFFFu, v, o);
        if (t == 0 && v != 0.0) atomicAdd(&g_sum, v);
    }
    __shared__ bool last;
    if (t == 0) {
        __threadfence();
        last = (atomicAdd(&g_done, 1u) == gridDim.x - 1);
    }
    __syncthreads();
    if (last && t == 0) {
        __threadfence();
        double denom = (double)(n > 0u ? n : 1u);
        out[0] = (float)(*(volatile double*)&g_sum / denom);
    }
}

// ---------------------------------------------------------------------------
extern "C" void kernel_launch(void* const* d_in, const int* in_sizes, int n_in,
                              void* d_out, int out_size)
{
    const float* pos  = (const float*)d_in[0];   // node_positions (B*N, 2)
    // d_in[1] = adjacency: unused
    const int*   eidx = (const int*)d_in[2];     // edge_index (2, E)
    float* out = (float*)d_out;

    int E = in_sizes[2] / 2;
    if (E > EMAX) E = EMAX;

    k_setup<<<32, 256>>>(pos, eidx, E);
    k_fill<<<16, 256>>>(E);
    k_enum<<<256, 512>>>(E);
    k_select_loss<<<SELGRID, 512>>>(out);
}